// round 9
// baseline (speedup 1.0000x reference)
#include <cuda_runtime.h>

// LSTM: T=512, B=4096, IN=1, H=12.
// R8 layout: ONE WARP PER BATCH ELEMENT (4096 warps, 2x occupancy vs R6).
// Lane l (<24): unit u=l%12, pair p=l/12 owns gate rows {24p+u, 24p+12+u}:
//   p=0 -> i,f rows;  p=1 -> g,o rows.
// Unified activation act(v) = c0 + c1*rcp(ex2(k*v)+1) covers sigmoid AND tanh
// with per-lane constants -> 3 EX2 + 3 RCP warp-ops per step total.
// h broadcast via double-buffered smem (STS + syncwarp + LDS.64 pairs).
// Matvecs use packed fp32x2 FMA.

#define T_STEPS 512
#define BATCH   4096
#define HID     12
#define LOG2E   1.4426950408889634f

typedef unsigned long long ull;

__device__ __forceinline__ ull pack2(float lo, float hi) {
    ull r;
    asm("mov.b64 %0, {%1, %2};" : "=l"(r) : "f"(lo), "f"(hi));
    return r;
}
__device__ __forceinline__ void unpack2(ull v, float& lo, float& hi) {
    asm("mov.b64 {%0, %1}, %2;" : "=f"(lo), "=f"(hi) : "l"(v));
}
__device__ __forceinline__ ull fma2(ull a, ull b, ull c) {
    ull d;
    asm("fma.rn.f32x2 %0, %1, %2, %3;" : "=l"(d) : "l"(a), "l"(b), "l"(c));
    return d;
}
__device__ __forceinline__ float ex2f(float x) {
    float r; asm("ex2.approx.f32 %0, %1;" : "=f"(r) : "f"(x)); return r;
}
__device__ __forceinline__ float rcpf(float x) {
    float r; asm("rcp.approx.f32 %0, %1;" : "=f"(r) : "f"(x)); return r;
}

__global__ void __launch_bounds__(128, 7)
lstm_kernel(const float* __restrict__ X,
            const float* __restrict__ W_ih,
            const float* __restrict__ W_hh,
            const float* __restrict__ b_ih,
            const float* __restrict__ b_hh,
            const float* __restrict__ fc_w,
            const float* __restrict__ fc_b,
            float* __restrict__ Y)
{
    __shared__ float hsh[2][4][16];   // [buf][warp][unit], 16-padded

    const int tid = threadIdx.x;
    const int w   = tid >> 5;                    // warp within CTA (0..3)
    const int l   = tid & 31;                    // lane
    const int b   = blockIdx.x * 4 + w;          // batch element (1024*4 = 4096)
    const int u   = l % 12;                      // hidden unit
    const int p   = (l >= 12 && l < 24) ? 1 : 0; // row-pair group
    const int src = u + 12;                      // lane holding (g,o) for unit u

    // Rows: p=0 -> i (0..11), f (12..23);  p=1 -> g (24..35), o (36..47).
    const int row0 = 24 * p + u;
    const int row1 = 24 * p + 12 + u;

    // ---- Register-resident weights ----
    ull w0[6], w1[6];
#pragma unroll
    for (int k = 0; k < 6; ++k) {
        w0[k] = pack2(W_hh[row0 * HID + 2 * k], W_hh[row0 * HID + 2 * k + 1]);
        w1[k] = pack2(W_hh[row1 * HID + 2 * k], W_hh[row1 * HID + 2 * k + 1]);
    }
    const float wih0  = W_ih[row0];
    const float wih1  = W_ih[row1];
    const float bias0 = b_ih[row0] + b_hh[row0];
    const float bias1 = b_ih[row1] + b_hh[row1];

    // slot0 activation constants: p=0 -> sigmoid, p=1 -> tanh.
    const float k0 = (p == 0) ? -LOG2E : 2.0f * LOG2E;
    const float c0 = (p == 0) ? 0.0f : 1.0f;
    const float c1 = (p == 0) ? 1.0f : -2.0f;
    // slot1 is always sigmoid.

    const float fcw = (l < 12) ? fc_w[l] : 0.0f;
    const float fcb = fc_b[0];

    // ---- State ----
    ull h2[6];
#pragma unroll
    for (int k = 0; k < 6; ++k) h2[k] = 0ULL;    // h0 = 0
    float c = 0.0f;

    const float* xp = X + b;
    float*       yp = Y + b;
    float x = xp[0];

#pragma unroll 2
    for (int t = 0; t < T_STEPS; ++t) {
        // Prefetch next input (independent of recurrence).
        float xn = 0.0f;
        if (t + 1 < T_STEPS) xn = xp[BATCH];

        // ---- two gate-row dot products per lane (packed f32x2) ----
        ull acc0 = pack2(fmaf(x, wih0, bias0), 0.0f);
        ull acc1 = pack2(fmaf(x, wih1, bias1), 0.0f);
#pragma unroll
        for (int k = 0; k < 6; ++k) {
            acc0 = fma2(h2[k], w0[k], acc0);
            acc1 = fma2(h2[k], w1[k], acc1);
        }
        float l0, h0, l1, h1;
        unpack2(acc0, l0, h0);
        unpack2(acc1, l1, h1);
        const float g0 = l0 + h0;   // i (p=0) / g (p=1)
        const float g1 = l1 + h1;   // f (p=0) / o (p=1)

        // ---- unified activations (one SIMD formula for sigma and tanh) ----
        const float e0 = ex2f(g0 * k0);
        const float a0 = fmaf(c1, rcpf(e0 + 1.0f), c0);   // sigma(i) / tanh(g)
        const float e1 = ex2f(g1 * -LOG2E);
        const float a1 = rcpf(e1 + 1.0f);                 // sigma(f) / sigma(o)

        // ---- combine: lanes 0-11 fetch (g,o) from lane u+12 ----
        const float gg = __shfl_sync(0xFFFFFFFFu, a0, src, 32);
        const float og = __shfl_sync(0xFFFFFFFFu, a1, src, 32);

        // c' = f*c + i*g ;  h = o * tanh(c')   (meaningful in lanes 0-11)
        c = fmaf(a1, c, a0 * gg);
        const float ec = ex2f(2.0f * LOG2E * c);
        const float th = fmaf(-2.0f, rcpf(ec + 1.0f), 1.0f);
        const float h  = og * th;

        // ---- publish h to smem (double-buffered) ----
        const int buf = t & 1;
        if (l < 12) hsh[buf][w][l] = h;

        // ---- fc output: butterfly over lanes 0-15 (12-15 contribute 0) ----
        float r = (l < 12) ? fcw * h : 0.0f;
        r += __shfl_xor_sync(0xFFFFFFFFu, r, 8, 16);
        r += __shfl_xor_sync(0xFFFFFFFFu, r, 4, 16);
        r += __shfl_xor_sync(0xFFFFFFFFu, r, 2, 16);
        r += __shfl_xor_sync(0xFFFFFFFFu, r, 1, 16);
        if (l == 0) *yp = r + fcb;

        __syncwarp();

        // ---- gather h vector as packed pairs for next step ----
#pragma unroll
        for (int k = 0; k < 6; ++k)
            h2[k] = *(const ull*)&hsh[buf][w][2 * k];

        yp += BATCH;
        xp += BATCH;
        x = xn;
    }
}

extern "C" void kernel_launch(void* const* d_in, const int* in_sizes, int n_in,
                              void* d_out, int out_size)
{
    const float* X    = (const float*)d_in[0];
    const float* W_ih = (const float*)d_in[1];
    const float* W_hh = (const float*)d_in[2];
    const float* b_ih = (const float*)d_in[3];
    const float* b_hh = (const float*)d_in[4];
    const float* fc_w = (const float*)d_in[5];
    const float* fc_b = (const float*)d_in[6];
    float* Y = (float*)d_out;

    // 4096 batches, 1 warp each; 128 threads (4 warps) per CTA -> 1024 CTAs.
    lstm_kernel<<<1024, 128>>>(X, W_ih, W_hh, b_ih, b_hh, fc_w, fc_b, Y);
}

// round 13
// speedup vs baseline: 1.5524x; 1.5524x over previous
#include <cuda_runtime.h>

// LSTM: T=512, B=4096, IN=1, H=12.
// R9 = R6 layout (best: 201us) + MUFU.TANH activations.
// One 16-lane segment per batch element, 2 batch/warp; lane u<12 owns unit u.
// All weights register-resident; h exchanged via warp shuffles.
// sigmoid(x) = 0.5*tanh(x/2)+0.5 with the /2 PRE-FOLDED into i,f,o weight
// rows + biases at load time -> every activation is 1 MUFU.TANH (+1 FMA for
// sigmoids), cutting the per-step dependency chain ~2x.

#define T_STEPS 512
#define BATCH   4096
#define HID     12

typedef unsigned long long ull;

__device__ __forceinline__ ull pack2(float lo, float hi) {
    ull r;
    asm("mov.b64 %0, {%1, %2};" : "=l"(r) : "f"(lo), "f"(hi));
    return r;
}
__device__ __forceinline__ void unpack2(ull v, float& lo, float& hi) {
    asm("mov.b64 {%0, %1}, %2;" : "=f"(lo), "=f"(hi) : "l"(v));
}
__device__ __forceinline__ ull fma2(ull a, ull b, ull c) {
    ull d;
    asm("fma.rn.f32x2 %0, %1, %2, %3;" : "=l"(d) : "l"(a), "l"(b), "l"(c));
    return d;
}
// Single-instruction MUFU tanh (sm_75+).
__device__ __forceinline__ float tanh_mufu(float x) {
    float r; asm("tanh.approx.f32 %0, %1;" : "=f"(r) : "f"(x)); return r;
}

__global__ void __launch_bounds__(128, 4)
lstm_kernel(const float* __restrict__ X,
            const float* __restrict__ W_ih,
            const float* __restrict__ W_hh,
            const float* __restrict__ b_ih,
            const float* __restrict__ b_hh,
            const float* __restrict__ fc_w,
            const float* __restrict__ fc_b,
            float* __restrict__ Y)
{
    const int tid = threadIdx.x;
    const int ls  = tid & 15;                       // lane within 16-lane segment
    const int b   = blockIdx.x * 8 + (tid >> 4);    // batch element (512*8 = 4096)
    const int u   = (ls < 12) ? ls : 11;            // hidden unit (idle lanes clamp)

    // ---- Load per-unit weights into registers (once) ----
    // Gate order (PyTorch): i, f, g, o -> W_hh rows g*12+u.
    // Rows for sigmoid gates (i,f,o) are PRE-SCALED by 0.5 so that
    // sigma(v) = 0.5*tanh(v_scaled)+0.5 needs no extra multiply.
    ull   w2[4][6];
    float wih[4], bias[4];
#pragma unroll
    for (int g = 0; g < 4; ++g) {
        const int   row = g * HID + u;
        const float s   = (g == 2) ? 1.0f : 0.5f;   // g-gate (tanh) unscaled
#pragma unroll
        for (int k = 0; k < 6; ++k)
            w2[g][k] = pack2(s * W_hh[row * HID + 2 * k],
                             s * W_hh[row * HID + 2 * k + 1]);
        wih[g]  = s * W_ih[row];                    // IN == 1
        bias[g] = s * (b_ih[row] + b_hh[row]);
    }
    const float fcw = (ls < 12) ? fc_w[ls] : 0.0f;
    const float fcb = fc_b[0];

    // ---- State ----
    ull h2[6];
#pragma unroll
    for (int k = 0; k < 6; ++k) h2[k] = 0ULL;       // h0 = 0
    float c = 0.0f;

    const float* xp = X + b;
    float*       yp = Y + b;
    float x = xp[0];                                // x_0 (broadcast in segment)

#pragma unroll 2
    for (int t = 0; t < T_STEPS; ++t) {
        // Prefetch next timestep's input (independent of recurrence).
        float xn = 0.0f;
        if (t + 1 < T_STEPS) xn = xp[BATCH];

        // ---- gates = x*W_ih + bias + h @ W_hh^T (packed f32x2, 2x3-deep) ----
        float gate[4];
#pragma unroll
        for (int g = 0; g < 4; ++g) {
            ull acc_a = pack2(fmaf(x, wih[g], bias[g]), 0.0f);
            ull acc_b = pack2(0.0f, 0.0f);
#pragma unroll
            for (int k = 0; k < 3; ++k) {
                acc_a = fma2(h2[k],     w2[g][k],     acc_a);
                acc_b = fma2(h2[k + 3], w2[g][k + 3], acc_b);
            }
            float la, ha, lb, hb;
            unpack2(acc_a, la, ha);
            unpack2(acc_b, lb, hb);
            gate[g] = (la + ha) + (lb + hb);
        }

        // ---- activations: one MUFU.TANH each ----
        // c-path first (g, i, f); o queued early too (MUFU pipelines).
        const float gg = tanh_mufu(gate[2]);                    // tanh(g)
        const float ti = tanh_mufu(gate[0]);
        const float tf = tanh_mufu(gate[1]);
        const float to = tanh_mufu(gate[3]);
        const float ig = fmaf(0.5f, ti, 0.5f);                  // sigma(i)
        const float fg = fmaf(0.5f, tf, 0.5f);                  // sigma(f)
        const float og = fmaf(0.5f, to, 0.5f);                  // sigma(o)

        c = fmaf(fg, c, ig * gg);
        const float h = og * tanh_mufu(c);

        // ---- fc output: butterfly over the 16-lane segment ----
        float r = fcw * h;                                      // 0 on idle lanes
        r += __shfl_xor_sync(0xFFFFFFFFu, r, 8, 16);
        r += __shfl_xor_sync(0xFFFFFFFFu, r, 4, 16);
        r += __shfl_xor_sync(0xFFFFFFFFu, r, 2, 16);
        r += __shfl_xor_sync(0xFFFFFFFFu, r, 1, 16);
        if (ls == 0) *yp = r + fcb;

        // ---- gather new h across the 12 active lanes of this segment ----
        float hj[12];
#pragma unroll
        for (int j = 0; j < 12; ++j)
            hj[j] = __shfl_sync(0xFFFFFFFFu, h, j, 16);
#pragma unroll
        for (int k = 0; k < 6; ++k)
            h2[k] = pack2(hj[2 * k], hj[2 * k + 1]);

        yp += BATCH;
        xp += BATCH;
        x = xn;
    }
}

extern "C" void kernel_launch(void* const* d_in, const int* in_sizes, int n_in,
                              void* d_out, int out_size)
{
    const float* X    = (const float*)d_in[0];
    const float* W_ih = (const float*)d_in[1];
    const float* W_hh = (const float*)d_in[2];
    const float* b_ih = (const float*)d_in[3];
    const float* b_hh = (const float*)d_in[4];
    const float* fc_w = (const float*)d_in[5];
    const float* fc_b = (const float*)d_in[6];
    float* Y = (float*)d_out;

    // 4096 batches * 16 lanes = 65536 threads; 128 threads/block -> 512 blocks.
    lstm_kernel<<<512, 128>>>(X, W_ih, W_hh, b_ih, b_hh, fc_w, fc_b, Y);
}

// round 14
// speedup vs baseline: 1.5860x; 1.0216x over previous
#include <cuda_runtime.h>

// LSTM: T=512, B=4096, IN=1, H=12.
// R13: R9 core (MUFU.TANH, pre-scaled sigmoid rows, packed f32x2 matvec) +
// 2-WAY BATCH INTERLEAVING: each lane carries state for TWO batch elements
// (streams A/B) sharing the same register-resident weights -> 2 independent
// recurrence chains per warp fill each other's stall slots.
// Warp = 2 segments x 2 streams = 4 batch elements. 1024 warps, 256 CTAs.
// fc output = redundant packed register dot (no butterfly shuffles).

#define T_STEPS 512
#define BATCH   4096
#define HID     12

typedef unsigned long long ull;

__device__ __forceinline__ ull pack2(float lo, float hi) {
    ull r;
    asm("mov.b64 %0, {%1, %2};" : "=l"(r) : "f"(lo), "f"(hi));
    return r;
}
__device__ __forceinline__ void unpack2(ull v, float& lo, float& hi) {
    asm("mov.b64 {%0, %1}, %2;" : "=f"(lo), "=f"(hi) : "l"(v));
}
__device__ __forceinline__ ull fma2(ull a, ull b, ull c) {
    ull d;
    asm("fma.rn.f32x2 %0, %1, %2, %3;" : "=l"(d) : "l"(a), "l"(b), "l"(c));
    return d;
}
__device__ __forceinline__ float tanh_mufu(float x) {
    float r; asm("tanh.approx.f32 %0, %1;" : "=f"(r) : "f"(x)); return r;
}

__global__ void __launch_bounds__(128, 2)
lstm_kernel(const float* __restrict__ X,
            const float* __restrict__ W_ih,
            const float* __restrict__ W_hh,
            const float* __restrict__ b_ih,
            const float* __restrict__ b_hh,
            const float* __restrict__ fc_w,
            const float* __restrict__ fc_b,
            float* __restrict__ Y)
{
    const int tid = threadIdx.x;
    const int l   = tid & 31;
    const int ls  = l & 15;                      // lane within 16-lane segment
    const int gw  = blockIdx.x * 4 + (tid >> 5); // global warp (0..1023)
    // Segment s = l>>4 handles batches {base, base+1}; streams A/B.
    const int bA  = gw * 4 + ((l >> 4) << 1);    // stream A batch; B = bA+1
    const int u   = (ls < 12) ? ls : 11;         // hidden unit (idle lanes clamp)

    // ---- Register-resident weights (shared by both streams) ----
    // Gate order i,f,g,o; sigmoid rows (i,f,o) pre-scaled by 0.5 so that
    // sigma(v) = 0.5*tanh(v') + 0.5.
    ull   w2[4][6];
    float wih[4], bias[4];
#pragma unroll
    for (int g = 0; g < 4; ++g) {
        const int   row = g * HID + u;
        const float s   = (g == 2) ? 1.0f : 0.5f;
#pragma unroll
        for (int k = 0; k < 6; ++k)
            w2[g][k] = pack2(s * W_hh[row * HID + 2 * k],
                             s * W_hh[row * HID + 2 * k + 1]);
        wih[g]  = s * W_ih[row];
        bias[g] = s * (b_ih[row] + b_hh[row]);
    }
    ull fc2[6];
#pragma unroll
    for (int k = 0; k < 6; ++k)
        fc2[k] = pack2(fc_w[2 * k], fc_w[2 * k + 1]);
    const float fcb = fc_b[0];

    // ---- State: two independent streams ----
    ull h2A[6], h2B[6];
#pragma unroll
    for (int k = 0; k < 6; ++k) { h2A[k] = 0ULL; h2B[k] = 0ULL; }
    float cA = 0.0f, cB = 0.0f;

    const float* xp = X + bA;
    float*       yp = Y + bA;
    float xA = xp[0];
    float xB = xp[1];

#pragma unroll 2
    for (int t = 0; t < T_STEPS; ++t) {
        // Prefetch next inputs (independent of recurrence).
        float xnA = 0.0f, xnB = 0.0f;
        if (t + 1 < T_STEPS) { xnA = xp[BATCH]; xnB = xp[BATCH + 1]; }

        // ---- gates for both streams, interleaved (packed f32x2 dots) ----
        float gA[4], gB[4];
#pragma unroll
        for (int g = 0; g < 4; ++g) {
            ull accA = pack2(fmaf(xA, wih[g], bias[g]), 0.0f);
            ull accB = pack2(fmaf(xB, wih[g], bias[g]), 0.0f);
#pragma unroll
            for (int k = 0; k < 6; ++k) {
                accA = fma2(h2A[k], w2[g][k], accA);
                accB = fma2(h2B[k], w2[g][k], accB);
            }
            float la, ha, lb, hb;
            unpack2(accA, la, ha); gA[g] = la + ha;
            unpack2(accB, lb, hb); gB[g] = lb + hb;
        }

        // ---- activations: 1 MUFU.TANH each, streams interleaved ----
        const float ggA = tanh_mufu(gA[2]);
        const float ggB = tanh_mufu(gB[2]);
        const float igA = fmaf(0.5f, tanh_mufu(gA[0]), 0.5f);
        const float igB = fmaf(0.5f, tanh_mufu(gB[0]), 0.5f);
        const float fgA = fmaf(0.5f, tanh_mufu(gA[1]), 0.5f);
        const float fgB = fmaf(0.5f, tanh_mufu(gB[1]), 0.5f);
        const float ogA = fmaf(0.5f, tanh_mufu(gA[3]), 0.5f);
        const float ogB = fmaf(0.5f, tanh_mufu(gB[3]), 0.5f);

        cA = fmaf(fgA, cA, igA * ggA);
        cB = fmaf(fgB, cB, igB * ggB);
        const float hA = ogA * tanh_mufu(cA);
        const float hB = ogB * tanh_mufu(cB);

        // ---- gather new h vectors across the 12 active lanes ----
#pragma unroll
        for (int k = 0; k < 6; ++k) {
            const float a0 = __shfl_sync(0xFFFFFFFFu, hA, 2 * k,     16);
            const float a1 = __shfl_sync(0xFFFFFFFFu, hA, 2 * k + 1, 16);
            const float b0 = __shfl_sync(0xFFFFFFFFu, hB, 2 * k,     16);
            const float b1 = __shfl_sync(0xFFFFFFFFu, hB, 2 * k + 1, 16);
            h2A[k] = pack2(a0, a1);
            h2B[k] = pack2(b0, b1);
        }

        // ---- fc output: redundant packed dot on gathered h (no shuffles) ----
        ull yaA = pack2(fcb, 0.0f);
        ull yaB = pack2(fcb, 0.0f);
#pragma unroll
        for (int k = 0; k < 6; ++k) {
            yaA = fma2(h2A[k], fc2[k], yaA);
            yaB = fma2(h2B[k], fc2[k], yaB);
        }
        float ylA, yhA, ylB, yhB;
        unpack2(yaA, ylA, yhA);
        unpack2(yaB, ylB, yhB);
        if (ls == 0) { yp[0] = ylA + yhA; yp[1] = ylB + yhB; }

        yp += BATCH;
        xp += BATCH;
        xA = xnA;
        xB = xnB;
    }
}

extern "C" void kernel_launch(void* const* d_in, const int* in_sizes, int n_in,
                              void* d_out, int out_size)
{
    const float* X    = (const float*)d_in[0];
    const float* W_ih = (const float*)d_in[1];
    const float* W_hh = (const float*)d_in[2];
    const float* b_ih = (const float*)d_in[3];
    const float* b_hh = (const float*)d_in[4];
    const float* fc_w = (const float*)d_in[5];
    const float* fc_b = (const float*)d_in[6];
    float* Y = (float*)d_out;

    // 4096 batches / 4 per warp = 1024 warps; 128 threads/block -> 256 blocks.
    lstm_kernel<<<256, 128>>>(X, W_ih, W_hh, b_ih, b_hh, fc_w, fc_b, Y);
}

// round 15
// speedup vs baseline: 1.7035x; 1.0741x over previous
#include <cuda_runtime.h>

// LSTM: T=512, B=4096, IN=1, H=12.
// R14: R13 skeleton (2-stream ILP, 16-lane segments, MUFU.TANH, packed f32x2
// matvec, 1024 warps / 256 CTAs) with the 24-SHFL h-gather replaced by a
// double-buffered SMEM broadcast: 2 STS + syncwarp + 12 LDS.64 per warp-step.
// Cuts MIO-class ops ~45% (SHFL+pack -> STS/LDS pairs land directly as
// aligned f32x2 register pairs).

#define T_STEPS 512
#define BATCH   4096
#define HID     12

typedef unsigned long long ull;

__device__ __forceinline__ ull pack2(float lo, float hi) {
    ull r;
    asm("mov.b64 %0, {%1, %2};" : "=l"(r) : "f"(lo), "f"(hi));
    return r;
}
__device__ __forceinline__ void unpack2(ull v, float& lo, float& hi) {
    asm("mov.b64 {%0, %1}, %2;" : "=f"(lo), "=f"(hi) : "l"(v));
}
__device__ __forceinline__ ull fma2(ull a, ull b, ull c) {
    ull d;
    asm("fma.rn.f32x2 %0, %1, %2, %3;" : "=l"(d) : "l"(a), "l"(b), "l"(c));
    return d;
}
__device__ __forceinline__ float tanh_mufu(float x) {
    float r; asm("tanh.approx.f32 %0, %1;" : "=f"(r) : "f"(x)); return r;
}

__global__ void __launch_bounds__(128, 2)
lstm_kernel(const float* __restrict__ X,
            const float* __restrict__ W_ih,
            const float* __restrict__ W_hh,
            const float* __restrict__ b_ih,
            const float* __restrict__ b_hh,
            const float* __restrict__ fc_w,
            const float* __restrict__ fc_b,
            float* __restrict__ Y)
{
    // [buf][warp][stream][seg][16 floats] : 16-float padding keeps the two
    // segments' LDS.64 broadcasts on distinct banks (offset 16 words mod 32).
    __shared__ float hsh[2][4][2][2][16];

    const int tid = threadIdx.x;
    const int w   = tid >> 5;                    // warp in CTA (0..3)
    const int seg = (tid >> 4) & 1;              // 16-lane segment (0..1)
    const int ls  = tid & 15;                    // lane within segment
    const int gw  = blockIdx.x * 4 + w;          // global warp (0..1023)
    const int bA  = gw * 4 + seg * 2;            // stream A batch; B = bA+1
    const int u   = (ls < 12) ? ls : 11;         // hidden unit (idle lanes clamp)

    // ---- Register-resident weights (shared by both streams) ----
    // Gate order i,f,g,o; sigmoid rows (i,f,o) pre-scaled by 0.5 so that
    // sigma(v) = 0.5*tanh(v') + 0.5.
    ull   w2[4][6];
    float wih[4], bias[4];
#pragma unroll
    for (int g = 0; g < 4; ++g) {
        const int   row = g * HID + u;
        const float s   = (g == 2) ? 1.0f : 0.5f;
#pragma unroll
        for (int k = 0; k < 6; ++k)
            w2[g][k] = pack2(s * W_hh[row * HID + 2 * k],
                             s * W_hh[row * HID + 2 * k + 1]);
        wih[g]  = s * W_ih[row];
        bias[g] = s * (b_ih[row] + b_hh[row]);
    }
    ull fc2[6];
#pragma unroll
    for (int k = 0; k < 6; ++k)
        fc2[k] = pack2(fc_w[2 * k], fc_w[2 * k + 1]);
    const float fcb = fc_b[0];

    // Per-thread smem bases for this (warp, seg).
    float* const hbA0 = &hsh[0][w][0][seg][0];
    float* const hbB0 = &hsh[0][w][1][seg][0];
    float* const hbA1 = &hsh[1][w][0][seg][0];
    float* const hbB1 = &hsh[1][w][1][seg][0];

    // ---- State ----
    ull h2A[6], h2B[6];
#pragma unroll
    for (int k = 0; k < 6; ++k) { h2A[k] = 0ULL; h2B[k] = 0ULL; }
    float cA = 0.0f, cB = 0.0f;

    const float* xp = X + bA;
    float*       yp = Y + bA;
    float xA = xp[0];
    float xB = xp[1];

#pragma unroll 2
    for (int t = 0; t < T_STEPS; ++t) {
        // Prefetch next inputs (independent of recurrence).
        float xnA = 0.0f, xnB = 0.0f;
        if (t + 1 < T_STEPS) { xnA = xp[BATCH]; xnB = xp[BATCH + 1]; }

        // ---- gates for both streams, interleaved (packed f32x2 dots) ----
        float gA[4], gB[4];
#pragma unroll
        for (int g = 0; g < 4; ++g) {
            ull accA = pack2(fmaf(xA, wih[g], bias[g]), 0.0f);
            ull accB = pack2(fmaf(xB, wih[g], bias[g]), 0.0f);
#pragma unroll
            for (int k = 0; k < 6; ++k) {
                accA = fma2(h2A[k], w2[g][k], accA);
                accB = fma2(h2B[k], w2[g][k], accB);
            }
            float la, ha, lb, hb;
            unpack2(accA, la, ha); gA[g] = la + ha;
            unpack2(accB, lb, hb); gB[g] = lb + hb;
        }

        // ---- activations: 1 MUFU.TANH each, streams interleaved ----
        const float ggA = tanh_mufu(gA[2]);
        const float ggB = tanh_mufu(gB[2]);
        const float igA = fmaf(0.5f, tanh_mufu(gA[0]), 0.5f);
        const float igB = fmaf(0.5f, tanh_mufu(gB[0]), 0.5f);
        const float fgA = fmaf(0.5f, tanh_mufu(gA[1]), 0.5f);
        const float fgB = fmaf(0.5f, tanh_mufu(gB[1]), 0.5f);
        const float ogA = fmaf(0.5f, tanh_mufu(gA[3]), 0.5f);
        const float ogB = fmaf(0.5f, tanh_mufu(gB[3]), 0.5f);

        cA = fmaf(fgA, cA, igA * ggA);
        cB = fmaf(fgB, cB, igB * ggB);
        const float hA = ogA * tanh_mufu(cA);
        const float hB = ogB * tanh_mufu(cB);

        // ---- publish h (double-buffered smem broadcast) ----
        float* const hbA = (t & 1) ? hbA1 : hbA0;
        float* const hbB = (t & 1) ? hbB1 : hbB0;
        if (ls < 12) { hbA[ls] = hA; hbB[ls] = hB; }
        __syncwarp();

        // ---- gather h vectors as aligned f32x2 pairs (LDS.64 broadcast) ----
#pragma unroll
        for (int k = 0; k < 6; ++k) {
            h2A[k] = *(const ull*)(hbA + 2 * k);
            h2B[k] = *(const ull*)(hbB + 2 * k);
        }

        // ---- fc output: packed dot on gathered h (no shuffles) ----
        ull yaA = pack2(fcb, 0.0f);
        ull yaB = pack2(fcb, 0.0f);
#pragma unroll
        for (int k = 0; k < 6; ++k) {
            yaA = fma2(h2A[k], fc2[k], yaA);
            yaB = fma2(h2B[k], fc2[k], yaB);
        }
        float ylA, yhA, ylB, yhB;
        unpack2(yaA, ylA, yhA);
        unpack2(yaB, ylB, yhB);
        if (ls == 0) { yp[0] = ylA + yhA; yp[1] = ylB + yhB; }

        yp += BATCH;
        xp += BATCH;
        xA = xnA;
        xB = xnB;
    }
}

extern "C" void kernel_launch(void* const* d_in, const int* in_sizes, int n_in,
                              void* d_out, int out_size)
{
    const float* X    = (const float*)d_in[0];
    const float* W_ih = (const float*)d_in[1];
    const float* W_hh = (const float*)d_in[2];
    const float* b_ih = (const float*)d_in[3];
    const float* b_hh = (const float*)d_in[4];
    const float* fc_w = (const float*)d_in[5];
    const float* fc_b = (const float*)d_in[6];
    float* Y = (float*)d_out;

    // 4096 batches / 4 per warp = 1024 warps; 128 threads/block -> 256 blocks.
    lstm_kernel<<<256, 128>>>(X, W_ih, W_hh, b_ih, b_hh, fc_w, fc_b, Y);
}